// round 2
// baseline (speedup 1.0000x reference)
#include <cuda_runtime.h>
#include <cuda_bf16.h>

#define BINS 32
#define CZ   128
#define NCLS 66            // 2*BINS + 2
#define LSEQ 768
#define NB   2
#define TPB  256

// One block per (b, i) row. 8 warps/block, each warp handles one j per
// iteration (32 lanes x float4 = 128 floats = one C_Z vector).
__global__ __launch_bounds__(TPB) void relpos_kernel(
    const int*   __restrict__ ridx,   // [B, L] int32
    const int*   __restrict__ rmask,  // [B, L] bool widened to int32
    const float* __restrict__ W,      // [66, 128]
    const float* __restrict__ bias,   // [128]
    float*       __restrict__ out)    // [B, L, L, 128]
{
    __shared__ float wb[NCLS * CZ];   // W + b, 33792 B
    __shared__ int   rj[LSEQ];
    __shared__ int   mj[LSEQ];

    const int tid = threadIdx.x;

    // Build Wb = W + b cooperatively
    #pragma unroll 4
    for (int k = tid; k < NCLS * CZ; k += TPB)
        wb[k] = W[k] + bias[k & (CZ - 1)];

    const int row = blockIdx.x;        // 0 .. B*L-1
    const int b   = row / LSEQ;
    // cache this batch's residue row + mask row
    for (int k = tid; k < LSEQ; k += TPB) {
        rj[k] = ridx[b * LSEQ + k];
        mj[k] = rmask[b * LSEQ + k];
    }
    __syncthreads();

    const int  i    = row - b * LSEQ;
    const int  ri   = rj[i];
    const bool mi   = (mj[i] != 0);
    const int  lane = tid & 31;
    const int  warp = tid >> 5;

    float4* orow = reinterpret_cast<float4*>(out) + (size_t)row * LSEQ * (CZ / 4);

    #pragma unroll 2
    for (int j = warp; j < LSEQ; j += TPB / 32) {
        int d = rj[j] - ri;                         // diff[b,i,j] = r[j] - r[i]
        d = min(max(d, -BINS), BINS) + BINS + 1;    // class index in [1, 65]
        float4 v = *reinterpret_cast<const float4*>(&wb[d * CZ + lane * 4]);
        if (!(mi && (mj[j] != 0))) v = make_float4(0.f, 0.f, 0.f, 0.f);
        __stcs(&orow[(size_t)j * (CZ / 4) + lane], v);
    }
}

extern "C" void kernel_launch(void* const* d_in, const int* in_sizes, int n_in,
                              void* d_out, int out_size) {
    const int*   ridx  = (const int*)d_in[0];
    const int*   rmask = (const int*)d_in[1];
    const float* W     = (const float*)d_in[2];
    const float* bias  = (const float*)d_in[3];
    float*       out   = (float*)d_out;

    relpos_kernel<<<NB * LSEQ, TPB>>>(ridx, rmask, W, bias, out);
}